// round 14
// baseline (speedup 1.0000x reference)
#include <cuda_runtime.h>

// GRU_8211977470410 — bidirectional GRU (H=32, in=1), B=2048, T=512, MLP head.
// Backward direction collapses to ONE step (scan reverse=True: ys_b[-1] = GRU(0, x[T-1])).
//
// R13: slot-count minimization. Empirical law from R7..R12: aggregate issue is
// capped at ~0.48/SMSP for this (fma/alu rt=2)-dominated mix, so wall time ~
// total instructions issued. Cuts vs R12:
//  - magic-FADD folded into downstream FFMA constants (i2f = 1 IADD only)
//  - single 8-deep dp4a chains (no IADD3 joins; latency hidden at 3.46 w/SMSP)
//  - h-update as 0.5*fma(tz, h-n, h+n)
//  - 1 batch/warp, 2048 warps, 1024 blocks x 64 thr, single wave
// ~50 slots per batch-step (24 dp4a = int8 information floor).

#define HDIM 32
#define FULLMASK 0xffffffffu
typedef unsigned int u32;

#define MAGIC_F 12582912.0f          // 1.5 * 2^23
#define MAGIC_I 0x4B400000

__device__ __forceinline__ int dp4a(u32 a, u32 b, int c) {
    int d;
    asm("dp4a.s32.s32 %0, %1, %2, %3;" : "=r"(d) : "r"(a), "r"(b), "r"(c));
    return d;
}
__device__ __forceinline__ float tanhap(float x) {
    float r; asm("tanh.approx.f32 %0, %1;" : "=f"(r) : "f"(x)); return r;
}
__device__ __forceinline__ float sigm(float x) {
    return __fdividef(1.0f, 1.0f + __expf(-x));
}
__device__ __forceinline__ float tanh_fast(float x) {
    float e = __expf(2.0f * x);
    return 1.0f - __fdividef(2.0f, e + 1.0f);
}
__device__ __forceinline__ u32 packs8(int a, int b, int c, int d) {
    return (u32)(a & 0xFF) | ((u32)(b & 0xFF) << 8) |
           ((u32)(c & 0xFF) << 16) | ((u32)(d & 0xFF) << 24);
}

__global__ void __launch_bounds__(64)
gru_bidir_kernel(const float* __restrict__ x,
                 const float* __restrict__ Wih_f, const float* __restrict__ Whh_f,
                 const float* __restrict__ bih_f, const float* __restrict__ bhh_f,
                 const float* __restrict__ Wih_b, const float* __restrict__ bih_b,
                 const float* __restrict__ bhh_b,
                 const float* __restrict__ W1, const float* __restrict__ b1v,
                 const float* __restrict__ W2, const float* __restrict__ b2v,
                 float* __restrict__ out, int B, int T)
{
    __shared__ __align__(16) u32 xq[2][2][8];   // [warp][parity][8 words] h as s8
    __shared__ __align__(16) float scr[2][80];  // [warp] head scratch

    const int lane = threadIdx.x & 31;
    const int warp = threadIdx.x >> 5;
    int b = blockIdx.x * 2 + warp;
    const bool valid = (b < B);
    if (!valid) b = B - 1;

    const int rr = lane, rz = lane + HDIM, rn = lane + 2 * HDIM;

    // ---- quantize this lane's three W_hh rows to s8 (per-row scale) ----
    u32 wqR[8], wqZ[8], wqN[8];
    float kkR, kkZ, kkN;
    {
        const int rows[3] = { rr, rz, rn };
        u32* dst[3] = { wqR, wqZ, wqN };
        float kk[3];
#pragma unroll
        for (int g = 0; g < 3; g++) {
            const float* p = Whh_f + rows[g] * HDIM;
            float amax = 1e-12f;
#pragma unroll
            for (int j = 0; j < HDIM; j++) amax = fmaxf(amax, fabsf(p[j]));
            const float qs = 127.0f / amax;
#pragma unroll
            for (int i = 0; i < 8; i++) {
                dst[g][i] = packs8(__float2int_rn(p[4*i]     * qs),
                                   __float2int_rn(p[4*i + 1] * qs),
                                   __float2int_rn(p[4*i + 2] * qs),
                                   __float2int_rn(p[4*i + 3] * qs));
            }
            kk[g] = amax / (127.0f * 127.0f);
        }
        kkR = kk[0]; kkZ = kk[1]; kkN = kk[2];
    }
    // gate constants. r,z: tanh-half form, 0.5 folded; magic-FADD folded into biases.
    const float kRh  = 0.5f * kkR;
    const float kZh  = 0.5f * kkZ;
    const float kNh  = 0.5f * kkN;                    // 0.5 folded for r-compose trick
    const float wirH = 0.5f * Wih_f[rr];
    const float wizH = 0.5f * Wih_f[rz];
    const float bRm  = 0.5f * (bih_f[rr] + bhh_f[rr]) - kRh * MAGIC_F;
    const float bZm  = 0.5f * (bih_f[rz] + bhh_f[rz]) - kZh * MAGIC_F;
    const float bNm  = 0.5f * bhh_f[rn]              - kNh * MAGIC_F;
    const float winS = Wih_f[rn], binS = bih_f[rn];

    const float* xW = x + (size_t)b * T;

    reinterpret_cast<char*>(xq[warp][0])[lane] = 0;   // h = 0, parity 0
    __syncwarp();

    float hs = 0.0f;

    auto step = [&](float xv, int rp) {
        // ---- load h (32 x s8 = 32B) via 2x LDS.128 ----
        const uint4* q = reinterpret_cast<const uint4*>(xq[warp][rp]);
        uint4 qa = q[0], qb = q[1];
        u32 hw[8] = { qa.x, qa.y, qa.z, qa.w, qb.x, qb.y, qb.z, qb.w };

        // ---- matvec: 3 single 8-deep dp4a chains (s32 exact) ----
        int iR = 0, iZ = 0, iN = 0;
#pragma unroll
        for (int k = 0; k < 8; k++) {
            iR = dp4a(wqR[k], hw[k], iR);
            iZ = dp4a(wqZ[k], hw[k], iZ);
            iN = dp4a(wqN[k], hw[k], iN);
        }

        // ---- int->float: magic IADD only (FADD folded into FFMA constants) ----
        const float rawR = __uint_as_float((u32)(MAGIC_I + iR));
        const float rawZ = __uint_as_float((u32)(MAGIC_I + iZ));
        const float rawN = __uint_as_float((u32)(MAGIC_I + iN));

        // r,z tanh-half args: raw*k + (x*wH + bm)
        const float tr = tanhap(fmaf(rawR, kRh, fmaf(xv, wirH, bRm)));
        const float tz = tanhap(fmaf(rawZ, kZh, fmaf(xv, wizH, bZm)));
        // n: r*inner + x*win + bin, r = 0.5+0.5*tr, inh = 0.5*inner
        const float inh  = fmaf(rawN, kNh, bNm);
        const float base = inh + fmaf(xv, winS, binS);
        const float n    = tanhap(fmaf(tr, inh, base));
        // h' = z*(h-n)+n, z = 0.5+0.5*tz  =>  h' = 0.5*( tz*(h-n) + (h+n) )
        const float d_ = hs - n;
        const float s_ = hs + n;
        hs = 0.5f * fmaf(tz, d_, s_);

        // ---- quantize via magic FFMA; STS.U8 of low mantissa byte ----
        const u32 qh = __float_as_uint(fmaf(hs, 127.0f, MAGIC_F));
        reinterpret_cast<char*>(xq[warp][rp ^ 1])[lane] = (char)(qh & 0xFF);
        __syncwarp();
    };

    // ---- main scan, 4 steps/iter, float4 x prefetch (parity 0,1,0,1) ----
    const float4* x4 = reinterpret_cast<const float4*>(xW);
    const int nIt = T >> 2;
    float4 c = x4[0];
    for (int it = 0; it < nIt; ++it) {
        int nx = (it + 1 < nIt) ? it + 1 : it;
        float4 nxt = x4[nx];
        step(c.x, 0);
        step(c.y, 1);
        step(c.z, 0);
        step(c.w, 1);
        c = nxt;
    }
    for (int t = nIt << 2; t < T; ++t) step(xW[t], t & 1);   // T%4 remainder

    // ---- backward direction: ONE step from h=0 on x[T-1], fp32 (W_hh_b unused) ----
    const float xl = xW[T - 1];
    const float rb = sigm(fmaf(xl, Wih_b[rr], bih_b[rr]) + bhh_b[rr]);
    const float zb = sigm(fmaf(xl, Wih_b[rz], bih_b[rz]) + bhh_b[rz]);
    const float nb = tanh_fast(fmaf(rb, bhh_b[rn], fmaf(xl, Wih_b[rn], bih_b[rn])));
    const float hb = (1.0f - zb) * nb;

    // ---- MLP head (fp32, per warp) ----
    float* sc = scr[warp];
    sc[lane] = hs;
    sc[32 + lane] = hb;
    __syncwarp();

    if (lane < 16) {
        const float4* w4 = reinterpret_cast<const float4*>(W1 + lane * 64);
        float a = b1v[lane];
#pragma unroll
        for (int i = 0; i < 16; i++) {
            float4 w = w4[i];
            a = fmaf(w.x, sc[4*i],   a);
            a = fmaf(w.y, sc[4*i+1], a);
            a = fmaf(w.z, sc[4*i+2], a);
            a = fmaf(w.w, sc[4*i+3], a);
        }
        sc[64 + lane] = fmaxf(a, 0.0f);
    }
    __syncwarp();

    float v = (lane < 16) ? W2[lane] * sc[64 + lane] : 0.0f;
#pragma unroll
    for (int o = 16; o > 0; o >>= 1) v += __shfl_xor_sync(FULLMASK, v, o);

    if (lane == 0 && valid) out[b] = sigm(v + b2v[0]);
}

extern "C" void kernel_launch(void* const* d_in, const int* in_sizes, int n_in,
                              void* d_out, int out_size) {
    const float* x     = (const float*)d_in[0];
    const float* Wih_f = (const float*)d_in[1];
    const float* Whh_f = (const float*)d_in[2];
    const float* bih_f = (const float*)d_in[3];
    const float* bhh_f = (const float*)d_in[4];
    const float* Wih_b = (const float*)d_in[5];
    // d_in[6] = W_hh_b: mathematically unused (backward output at T-1 starts from h=0)
    const float* bih_b = (const float*)d_in[7];
    const float* bhh_b = (const float*)d_in[8];
    const float* W1    = (const float*)d_in[9];
    const float* b1v   = (const float*)d_in[10];
    const float* W2    = (const float*)d_in[11];
    const float* b2v   = (const float*)d_in[12];

    int B = out_size;                // output [B,1] fp32
    int T = in_sizes[0] / B;         // x is [B,T,1]

    int grid = (B + 1) / 2;          // 2 warps/block, 1 batch per warp, single wave
    gru_bidir_kernel<<<grid, 64>>>(x, Wih_f, Whh_f, bih_f, bhh_f,
                                   Wih_b, bih_b, bhh_b,
                                   W1, b1v, W2, b2v,
                                   (float*)d_out, B, T);
}

// round 15
// speedup vs baseline: 1.1748x; 1.1748x over previous
#include <cuda_runtime.h>

// GRU_8211977470410 — bidirectional GRU (H=32, in=1), B=2048, T=512, MLP head.
// Backward direction collapses to ONE step (scan reverse=True: ys_b[-1] = GRU(0, x[T-1])).
//
// R14 = R12 (2 batches/warp — fixed per-step costs amortized; R13 showed
// 1-batch/warp re-doubles sync/loop overhead per batch and loses) + R13's
// verified epilogue trims:
//   - magic-FADD folded into FFMA bias constants (i2f = single IADD)
//   - single 8-deep dp4a chains (no IADD3 joins; latency hidden by 2 indep batches)
//   - h-update as 0.5*fma(tz, h-n, h+n)
// dp4a int8 matvec (4 MACs/slot, s32 exact); gates fp32 tanh.approx.f32;
// sigmoid = 0.5 + 0.5*tanh(pre/2) with 0.5 pre-folded.
// 512 blocks x 64 thr (1024 warps, single wave).

#define HDIM 32
#define FULLMASK 0xffffffffu
typedef unsigned int u32;

#define MAGIC_F 12582912.0f          // 1.5 * 2^23
#define MAGIC_I 0x4B400000

__device__ __forceinline__ int dp4a(u32 a, u32 b, int c) {
    int d;
    asm("dp4a.s32.s32 %0, %1, %2, %3;" : "=r"(d) : "r"(a), "r"(b), "r"(c));
    return d;
}
__device__ __forceinline__ float tanhap(float x) {
    float r; asm("tanh.approx.f32 %0, %1;" : "=f"(r) : "f"(x)); return r;
}
__device__ __forceinline__ float sigm(float x) {
    return __fdividef(1.0f, 1.0f + __expf(-x));
}
__device__ __forceinline__ float tanh_fast(float x) {
    float e = __expf(2.0f * x);
    return 1.0f - __fdividef(2.0f, e + 1.0f);
}
__device__ __forceinline__ u32 packs8(int a, int b, int c, int d) {
    return (u32)(a & 0xFF) | ((u32)(b & 0xFF) << 8) |
           ((u32)(c & 0xFF) << 16) | ((u32)(d & 0xFF) << 24);
}

__global__ void __launch_bounds__(64)
gru_bidir_kernel(const float* __restrict__ x,
                 const float* __restrict__ Wih_f, const float* __restrict__ Whh_f,
                 const float* __restrict__ bih_f, const float* __restrict__ bhh_f,
                 const float* __restrict__ Wih_b, const float* __restrict__ bih_b,
                 const float* __restrict__ bhh_b,
                 const float* __restrict__ W1, const float* __restrict__ b1v,
                 const float* __restrict__ W2, const float* __restrict__ b2v,
                 float* __restrict__ out, int B, int T)
{
    // [warp][parity][batchA 8 words | batchB 8 words] : h as s8
    __shared__ __align__(16) u32 xq[2][2][16];
    __shared__ __align__(16) float scr[2][2][80];  // [warp][batch] concat(64)+h1(16)

    const int lane = threadIdx.x & 31;
    const int warp = threadIdx.x >> 5;
    int bA = blockIdx.x * 4 + warp * 2;
    int bB = bA + 1;
    const bool vA = (bA < B), vB = (bB < B);
    if (!vA) bA = B - 1;
    if (!vB) bB = B - 1;

    const int rr = lane, rz = lane + HDIM, rn = lane + 2 * HDIM;

    // ---- quantize this lane's three W_hh rows to s8 (per-row scale) ----
    u32 wqR[8], wqZ[8], wqN[8];
    float kkR, kkZ, kkN;
    {
        const int rows[3] = { rr, rz, rn };
        u32* dst[3] = { wqR, wqZ, wqN };
        float kk[3];
#pragma unroll
        for (int g = 0; g < 3; g++) {
            const float* p = Whh_f + rows[g] * HDIM;
            float amax = 1e-12f;
#pragma unroll
            for (int j = 0; j < HDIM; j++) amax = fmaxf(amax, fabsf(p[j]));
            const float qs = 127.0f / amax;
#pragma unroll
            for (int i = 0; i < 8; i++) {
                dst[g][i] = packs8(__float2int_rn(p[4*i]     * qs),
                                   __float2int_rn(p[4*i + 1] * qs),
                                   __float2int_rn(p[4*i + 2] * qs),
                                   __float2int_rn(p[4*i + 3] * qs));
            }
            kk[g] = amax / (127.0f * 127.0f);
        }
        kkR = kk[0]; kkZ = kk[1]; kkN = kk[2];
    }
    // gate constants: tanh-half form (0.5 folded) + magic-FADD folded into biases
    const float kRh  = 0.5f * kkR;
    const float kZh  = 0.5f * kkZ;
    const float kNh  = 0.5f * kkN;
    const float wirH = 0.5f * Wih_f[rr];
    const float wizH = 0.5f * Wih_f[rz];
    const float bRm  = 0.5f * (bih_f[rr] + bhh_f[rr]) - kRh * MAGIC_F;
    const float bZm  = 0.5f * (bih_f[rz] + bhh_f[rz]) - kZh * MAGIC_F;
    const float bNm  = 0.5f * bhh_f[rn]              - kNh * MAGIC_F;
    const float winS = Wih_f[rn], binS = bih_f[rn];

    const float* xA = x + (size_t)bA * T;
    const float* xB = x + (size_t)bB * T;

    // init h = 0 in parity-0 buffer (one byte per lane per batch)
    {
        char* p0 = reinterpret_cast<char*>(xq[warp][0]);
        p0[lane] = 0;
        p0[32 + lane] = 0;
    }
    __syncwarp();

    float hsA = 0.0f, hsB = 0.0f;

    auto step = [&](float xav, float xbv, int rp) {
        // ---- load h for both batches: 64B via 4x LDS.128 (broadcast) ----
        const uint4* q = reinterpret_cast<const uint4*>(xq[warp][rp]);
        uint4 a0 = q[0], a1 = q[1];            // batch A words 0..7
        uint4 b0 = q[2], b1 = q[3];            // batch B words 0..7
        u32 hA[8] = { a0.x, a0.y, a0.z, a0.w, a1.x, a1.y, a1.z, a1.w };
        u32 hB[8] = { b0.x, b0.y, b0.z, b0.w, b1.x, b1.y, b1.z, b1.w };

        // ---- matvec: 6 single 8-deep dp4a chains (2 batches x 3 gates) ----
        int iRA = 0, iZA = 0, iNA = 0;
        int iRB = 0, iZB = 0, iNB = 0;
#pragma unroll
        for (int k = 0; k < 8; k++) {
            iRA = dp4a(wqR[k], hA[k], iRA);
            iRB = dp4a(wqR[k], hB[k], iRB);
            iZA = dp4a(wqZ[k], hA[k], iZA);
            iZB = dp4a(wqZ[k], hB[k], iZB);
            iNA = dp4a(wqN[k], hA[k], iNA);
            iNB = dp4a(wqN[k], hB[k], iNB);
        }

        // ---- int->float via magic IADD only (FADD folded into biases) ----
        const float rawRA = __uint_as_float((u32)(MAGIC_I + iRA));
        const float rawZA = __uint_as_float((u32)(MAGIC_I + iZA));
        const float rawNA = __uint_as_float((u32)(MAGIC_I + iNA));
        const float rawRB = __uint_as_float((u32)(MAGIC_I + iRB));
        const float rawZB = __uint_as_float((u32)(MAGIC_I + iZB));
        const float rawNB = __uint_as_float((u32)(MAGIC_I + iNB));

        // ---- gates fp32, batch A ----
        const float trA  = tanhap(fmaf(rawRA, kRh, fmaf(xav, wirH, bRm)));
        const float tzA  = tanhap(fmaf(rawZA, kZh, fmaf(xav, wizH, bZm)));
        const float inhA = fmaf(rawNA, kNh, bNm);
        const float nA   = tanhap(fmaf(trA, inhA, inhA + fmaf(xav, winS, binS)));
        const float dA = hsA - nA, sA = hsA + nA;
        hsA = 0.5f * fmaf(tzA, dA, sA);

        // ---- gates fp32, batch B ----
        const float trB  = tanhap(fmaf(rawRB, kRh, fmaf(xbv, wirH, bRm)));
        const float tzB  = tanhap(fmaf(rawZB, kZh, fmaf(xbv, wizH, bZm)));
        const float inhB = fmaf(rawNB, kNh, bNm);
        const float nB   = tanhap(fmaf(trB, inhB, inhB + fmaf(xbv, winS, binS)));
        const float dB = hsB - nB, sB = hsB + nB;
        hsB = 0.5f * fmaf(tzB, dB, sB);

        // ---- quantize via magic FFMA; STS.U8 of low mantissa byte ----
        const u32 qhA = __float_as_uint(fmaf(hsA, 127.0f, MAGIC_F));
        const u32 qhB = __float_as_uint(fmaf(hsB, 127.0f, MAGIC_F));
        char* pw = reinterpret_cast<char*>(xq[warp][rp ^ 1]);
        pw[lane]      = (char)(qhA & 0xFF);
        pw[32 + lane] = (char)(qhB & 0xFF);
        __syncwarp();
    };

    // ---- main scan, 4 steps/iter, float4 x prefetch (parity 0,1,0,1) ----
    const float4* x4A = reinterpret_cast<const float4*>(xA);
    const float4* x4B = reinterpret_cast<const float4*>(xB);
    const int nIt = T >> 2;
    float4 ca = x4A[0], cb = x4B[0];
    for (int it = 0; it < nIt; ++it) {
        int nx = (it + 1 < nIt) ? it + 1 : it;
        float4 na = x4A[nx], nb = x4B[nx];
        step(ca.x, cb.x, 0);
        step(ca.y, cb.y, 1);
        step(ca.z, cb.z, 0);
        step(ca.w, cb.w, 1);
        ca = na; cb = nb;
    }
    for (int t = nIt << 2; t < T; ++t) step(xA[t], xB[t], t & 1);   // T%4 remainder

    // ---- backward direction: ONE step from h=0 on x[T-1], fp32 (W_hh_b unused) ----
    const float wibr = Wih_b[rr], wibz = Wih_b[rz], wibn = Wih_b[rn];
    const float bibr = bih_b[rr], bibz = bih_b[rz], bibn = bih_b[rn];
    const float bhbr = bhh_b[rr], bhbz = bhh_b[rz], bhbn = bhh_b[rn];
    const float xlA = xA[T - 1], xlB = xB[T - 1];

    const float rbA = sigm(fmaf(xlA, wibr, bibr) + bhbr);
    const float zbA = sigm(fmaf(xlA, wibz, bibz) + bhbz);
    const float nbA = tanh_fast(fmaf(rbA, bhbn, fmaf(xlA, wibn, bibn)));
    const float hbA = (1.0f - zbA) * nbA;

    const float rbB = sigm(fmaf(xlB, wibr, bibr) + bhbr);
    const float zbB = sigm(fmaf(xlB, wibz, bibz) + bhbz);
    const float nbB = tanh_fast(fmaf(rbB, bhbn, fmaf(xlB, wibn, bibn)));
    const float hbB = (1.0f - zbB) * nbB;

    // ---- MLP head (fp32), two batches per warp ----
    scr[warp][0][lane] = hsA; scr[warp][0][32 + lane] = hbA;
    scr[warp][1][lane] = hsB; scr[warp][1][32 + lane] = hbB;
    __syncwarp();

    if (lane < 16) {
        const float4* w4 = reinterpret_cast<const float4*>(W1 + lane * 64);
        float a0 = b1v[lane], a1 = a0;
        const float* s0 = scr[warp][0];
        const float* s1 = scr[warp][1];
#pragma unroll
        for (int i = 0; i < 16; i++) {
            float4 w = w4[i];
            a0 = fmaf(w.x, s0[4*i], a0);   a0 = fmaf(w.y, s0[4*i+1], a0);
            a0 = fmaf(w.z, s0[4*i+2], a0); a0 = fmaf(w.w, s0[4*i+3], a0);
            a1 = fmaf(w.x, s1[4*i], a1);   a1 = fmaf(w.y, s1[4*i+1], a1);
            a1 = fmaf(w.z, s1[4*i+2], a1); a1 = fmaf(w.w, s1[4*i+3], a1);
        }
        scr[warp][0][64 + lane] = fmaxf(a0, 0.0f);
        scr[warp][1][64 + lane] = fmaxf(a1, 0.0f);
    }
    __syncwarp();

    float v0 = (lane < 16) ? W2[lane] * scr[warp][0][64 + lane] : 0.0f;
    float v1 = (lane < 16) ? W2[lane] * scr[warp][1][64 + lane] : 0.0f;
#pragma unroll
    for (int o = 16; o > 0; o >>= 1) {
        v0 += __shfl_xor_sync(FULLMASK, v0, o);
        v1 += __shfl_xor_sync(FULLMASK, v1, o);
    }
    if (lane == 0) {
        float bb2 = b2v[0];
        if (vA) out[bA] = sigm(v0 + bb2);
        if (vB) out[bB] = sigm(v1 + bb2);
    }
}

extern "C" void kernel_launch(void* const* d_in, const int* in_sizes, int n_in,
                              void* d_out, int out_size) {
    const float* x     = (const float*)d_in[0];
    const float* Wih_f = (const float*)d_in[1];
    const float* Whh_f = (const float*)d_in[2];
    const float* bih_f = (const float*)d_in[3];
    const float* bhh_f = (const float*)d_in[4];
    const float* Wih_b = (const float*)d_in[5];
    // d_in[6] = W_hh_b: mathematically unused (backward output at T-1 starts from h=0)
    const float* bih_b = (const float*)d_in[7];
    const float* bhh_b = (const float*)d_in[8];
    const float* W1    = (const float*)d_in[9];
    const float* b1v   = (const float*)d_in[10];
    const float* W2    = (const float*)d_in[11];
    const float* b2v   = (const float*)d_in[12];

    int B = out_size;                // output [B,1] fp32
    int T = in_sizes[0] / B;         // x is [B,T,1]

    int grid = (B + 3) / 4;          // 2 warps/block, 2 batches per warp
    gru_bidir_kernel<<<grid, 64>>>(x, Wih_f, Whh_f, bih_f, bhh_f,
                                   Wih_b, bih_b, bhh_b,
                                   W1, b1v, W2, b2v,
                                   (float*)d_out, B, T);
}